// round 12
// baseline (speedup 1.0000x reference)
#include <cuda_runtime.h>
#include <cuda_bf16.h>
#include <cstdint>

#define Bsz  256
#define Tlen 2048
#define Idim 128
#define Hdim 64
#define Gdim 256                       // 4*H
#define Mrows (Bsz * Tlen)             // 524288

// Scratch (static device arrays: allocation-free per harness rules)
__device__ float g_pre[(size_t)Mrows * Gdim];   // 512 MiB: pre-activations
__device__ float g_h0 [(size_t)Mrows * Hdim];   // 128 MiB: layer output ping
__device__ float g_h1 [(size_t)Mrows * Hdim];   // 128 MiB: layer output pong

__device__ __forceinline__ float sigm_f(float x) {
    return 1.0f / (1.0f + __expf(-x));
}
__device__ __forceinline__ float tanh_f(float x) {
    return 2.0f / (1.0f + __expf(-2.0f * x)) - 1.0f;
}

// ---------------------------------------------------------------------------
// packed f32x2 helpers (base-profile sm_100+ PTX, plain sm_103 target OK)
// ---------------------------------------------------------------------------
typedef unsigned long long u64;

__device__ __forceinline__ u64 pk2(float x, float y) {
    u64 r;
    asm("mov.b64 %0, {%1, %2};" : "=l"(r) : "f"(x), "f"(y));
    return r;
}
__device__ __forceinline__ void upk2(float& x, float& y, u64 v) {
    asm("mov.b64 {%0, %1}, %2;" : "=f"(x), "=f"(y) : "l"(v));
}
__device__ __forceinline__ u64 fma2(u64 a, u64 b, u64 c) {
    u64 d;
    asm("fma.rn.f32x2 %0, %1, %2, %3;" : "=l"(d) : "l"(a), "l"(b), "l"(c));
    return d;
}
__device__ __forceinline__ u64 add2(u64 a, u64 b) {
    u64 d;
    asm("add.rn.f32x2 %0, %1, %2;" : "=l"(d) : "l"(a), "l"(b));
    return d;
}
__device__ __forceinline__ u64 mul2(u64 a, u64 b) {
    u64 d;
    asm("mul.rn.f32x2 %0, %1, %2;" : "=l"(d) : "l"(a), "l"(b));
    return d;
}
__device__ __forceinline__ void lds_v2(u64& a, u64& b, uint32_t addr) {
    asm volatile("ld.shared.v2.u64 {%0, %1}, [%2];"
                 : "=l"(a), "=l"(b) : "r"(addr));
}

// ---------------------------------------------------------------------------
// mma.sync helpers (baseline PTX — works on plain sm_103 target)
// ---------------------------------------------------------------------------
__device__ __forceinline__ void ldsm_x4(uint32_t* r, uint32_t addr) {
    asm volatile("ldmatrix.sync.aligned.m8n8.x4.shared.b16 {%0,%1,%2,%3}, [%4];"
                 : "=r"(r[0]), "=r"(r[1]), "=r"(r[2]), "=r"(r[3]) : "r"(addr));
}
__device__ __forceinline__ void mma16816(float* d, const uint32_t* a, const uint32_t* b) {
    asm volatile(
        "mma.sync.aligned.m16n8k16.row.col.f32.bf16.bf16.f32 "
        "{%0,%1,%2,%3}, {%4,%5,%6,%7}, {%8,%9}, {%0,%1,%2,%3};"
        : "+f"(d[0]), "+f"(d[1]), "+f"(d[2]), "+f"(d[3])
        : "r"(a[0]), "r"(a[1]), "r"(a[2]), "r"(a[3]), "r"(b[0]), "r"(b[1]));
}

// ===========================================================================
// GEMM: g_pre[m, n] = sum_k A[m,k]*W[n,k] + bih[n] + bhh[n]
// Block tile M=64 x N=256 (full N), K-chunks of 32, split-bf16 3-term.
// (unchanged — measured ~0.9 ms total for 3 layers)
// ===========================================================================
#define SMA_HI 0
#define SMA_LO 5120
#define SMW_HI 10240
#define SMW_LO 30720
#define GSM_TOTAL 51200

__global__ __launch_bounds__(256, 2) void gemm_mma_kernel(
    const float* __restrict__ Aext, int sel,
    const float* __restrict__ W,
    const float* __restrict__ bih, const float* __restrict__ bhh,
    int K)
{
    extern __shared__ char smem[];
    const uint32_t sbase = (uint32_t)__cvta_generic_to_shared(smem);

    const float* A = (sel == 0) ? Aext : ((sel == 1) ? g_h0 : g_h1);

    const int t   = threadIdx.x;
    const int wid = t >> 5;
    const int lid = t & 31;
    const int wm  = wid >> 2;          // 0..1 : warp row   (32 M each)
    const int wn  = wid & 3;           // 0..3 : warp col   (64 N each)
    const size_t m0 = (size_t)blockIdx.x * 64;

    float acc[2][8][4];
#pragma unroll
    for (int i = 0; i < 2; i++)
#pragma unroll
        for (int j = 0; j < 8; j++)
#pragma unroll
            for (int v = 0; v < 4; v++) acc[i][j][v] = 0.0f;

    // per-lane ldmatrix address components (stride 40 bf16 = 80B per row)
    const int rowA = wm * 32 + (lid & 7) + ((lid >> 3) & 1) * 8;
    const int colA = (lid >> 4) * 8;
    const int rowB = wn * 64 + (lid >> 4) * 8 + (lid & 7);
    const int colB = ((lid >> 3) & 1) * 8;

    const int nchunks = K >> 5;
    for (int c = 0; c < nchunks; c++) {
        const int k0 = c << 5;

        // ---- load + split-convert A tile (64 x 32): 512 float4, 2/thread ----
#pragma unroll
        for (int i = 0; i < 2; i++) {
            int f   = t + i * 256;
            int row = f >> 3;
            int c4  = (f & 7) << 2;
            float4 v = *(const float4*)&A[(m0 + row) * K + k0 + c4];
            __nv_bfloat162 h0 = __floats2bfloat162_rn(v.x, v.y);
            __nv_bfloat162 h1 = __floats2bfloat162_rn(v.z, v.w);
            __nv_bfloat162 l0 = __floats2bfloat162_rn(v.x - __bfloat162float(h0.x),
                                                      v.y - __bfloat162float(h0.y));
            __nv_bfloat162 l1 = __floats2bfloat162_rn(v.z - __bfloat162float(h1.x),
                                                      v.w - __bfloat162float(h1.y));
            uint32_t off = (uint32_t)(row * 40 + c4) * 2;
            *(uint2*)(smem + SMA_HI + off) =
                make_uint2(*(uint32_t*)&h0, *(uint32_t*)&h1);
            *(uint2*)(smem + SMA_LO + off) =
                make_uint2(*(uint32_t*)&l0, *(uint32_t*)&l1);
        }
        // ---- load + split-convert W tile (256 x 32): 2048 float4, 8/thread ----
#pragma unroll
        for (int i = 0; i < 8; i++) {
            int f   = t + i * 256;
            int row = f >> 3;
            int c4  = (f & 7) << 2;
            float4 v = *(const float4*)&W[(size_t)row * K + k0 + c4];
            __nv_bfloat162 h0 = __floats2bfloat162_rn(v.x, v.y);
            __nv_bfloat162 h1 = __floats2bfloat162_rn(v.z, v.w);
            __nv_bfloat162 l0 = __floats2bfloat162_rn(v.x - __bfloat162float(h0.x),
                                                      v.y - __bfloat162float(h0.y));
            __nv_bfloat162 l1 = __floats2bfloat162_rn(v.z - __bfloat162float(h1.x),
                                                      v.w - __bfloat162float(h1.y));
            uint32_t off = (uint32_t)(row * 40 + c4) * 2;
            *(uint2*)(smem + SMW_HI + off) =
                make_uint2(*(uint32_t*)&h0, *(uint32_t*)&h1);
            *(uint2*)(smem + SMW_LO + off) =
                make_uint2(*(uint32_t*)&l0, *(uint32_t*)&l1);
        }
        __syncthreads();

        // ---- mma over the 32-deep chunk (2 k16 steps, 3 precision terms) ----
#pragma unroll
        for (int kt = 0; kt < 2; kt++) {
            uint32_t afh[2][4], afl[2][4];
#pragma unroll
            for (int mt = 0; mt < 2; mt++) {
                uint32_t ao = (uint32_t)((rowA + mt * 16) * 40 + colA + kt * 16) * 2;
                ldsm_x4(afh[mt], sbase + SMA_HI + ao);
                ldsm_x4(afl[mt], sbase + SMA_LO + ao);
            }
#pragma unroll
            for (int nt2 = 0; nt2 < 4; nt2++) {
                uint32_t bo = (uint32_t)((rowB + nt2 * 16) * 40 + colB + kt * 16) * 2;
                uint32_t bfh[4], bfl[4];
                ldsm_x4(bfh, sbase + SMW_HI + bo);
                ldsm_x4(bfl, sbase + SMW_LO + bo);
#pragma unroll
                for (int mt = 0; mt < 2; mt++)
#pragma unroll
                    for (int half = 0; half < 2; half++) {
                        int nt = nt2 * 2 + half;
                        mma16816(acc[mt][nt], afh[mt], &bfh[half * 2]);  // hi*hi
                        mma16816(acc[mt][nt], afh[mt], &bfl[half * 2]);  // hi*lo
                        mma16816(acc[mt][nt], afl[mt], &bfh[half * 2]);  // lo*hi
                    }
            }
        }
        __syncthreads();
    }

    // ---- epilogue: d[row, n] + bias ----
    const int g  = lid >> 2;
    const int tg = lid & 3;
#pragma unroll
    for (int nt = 0; nt < 8; nt++) {
        int n = wn * 64 + nt * 8 + tg * 2;
        float b0 = bih[n]     + bhh[n];
        float b1 = bih[n + 1] + bhh[n + 1];
        size_t row0 = m0 + wm * 32 + g;
#pragma unroll
        for (int mt = 0; mt < 2; mt++) {
            size_t r0 = row0 + mt * 16;
            float2 o0 = make_float2(acc[mt][nt][0] + b0, acc[mt][nt][1] + b1);
            float2 o1 = make_float2(acc[mt][nt][2] + b0, acc[mt][nt][3] + b1);
            *(float2*)&g_pre[r0 * Gdim + n]       = o0;
            *(float2*)&g_pre[(r0 + 8) * Gdim + n] = o1;
        }
    }
}

// ===========================================================================
// Recurrent layer: 256 threads/block, one block per TWO batch elements
// processed as a PACKED f32x2 pair (lane .x = batch 2b, lane .y = batch 2b+1).
// Thread g = gate g for both batches; w_hh row pre-packed (w,w) in 64 b64 regs.
// h and gates live in smem as interleaved float2 pairs.
// MODE 0 -> g_h0; MODE 1 -> g_h1; MODE 2 -> fused FC head into out.
// ===========================================================================
template <int MODE>
__global__ __launch_bounds__(256) void lstm_rec_kernel(
    const float* __restrict__ w_hh,
    const float* __restrict__ fc_w, const float* __restrict__ fc_b,
    float* __restrict__ out)
{
    __shared__ __align__(16) float2 h2_s[64];      // (h_b0[k], h_b1[k])
    __shared__ __align__(16) float2 gate2_s[256];  // (v_b0[g], v_b1[g])

    const int g  = threadIdx.x;
    const int b2 = blockIdx.x;
    const int batch0 = 2 * b2, batch1 = 2 * b2 + 1;

    // packed weights (w,w): 64 x b64
    u64 w2[64];
#pragma unroll
    for (int k = 0; k < 64; k++) {
        float w = w_hh[(size_t)g * 64 + k];
        w2[k] = pk2(w, w);
    }

    u64 c2 = 0;                        // packed cell state = (0.0f, 0.0f)
    if (g < 64) h2_s[g] = make_float2(0.0f, 0.0f);

    float fwa = 0.0f, fwb = 0.0f, fcb = 0.0f;
    if (MODE == 2 && g < 32) {
        fwa = fc_w[g];
        fwb = fc_w[g + 32];
        fcb = fc_b[0];
    }
    __syncthreads();

    const float* pre0 = g_pre + (size_t)batch0 * Tlen * Gdim + g;
    const float* pre1 = g_pre + (size_t)batch1 * Tlen * Gdim + g;
    float* hout = (MODE == 0) ? g_h0 : g_h1;

    const uint32_t haddr = (uint32_t)__cvta_generic_to_shared(h2_s);

    float pn0 = pre0[0];
    float pn1 = pre1[0];

    for (int t = 0; t < Tlen; t++) {
        float pv0 = pn0, pv1 = pn1;
        if (t + 1 < Tlen) {
            pn0 = pre0[(size_t)(t + 1) * Gdim];
            pn1 = pre1[(size_t)(t + 1) * Gdim];
        }

        // packed dot product: 64 FFMA2, 32 x 16B LDS, 4 acc chains
        u64 acc0 = 0, acc1 = 0, acc2 = 0, acc3 = 0;
#pragma unroll
        for (int q = 0; q < 16; q++) {
            u64 p0, p1, p2, p3;
            lds_v2(p0, p1, haddr + q * 32);
            lds_v2(p2, p3, haddr + q * 32 + 16);
            acc0 = fma2(p0, w2[4 * q + 0], acc0);
            acc1 = fma2(p1, w2[4 * q + 1], acc1);
            acc2 = fma2(p2, w2[4 * q + 2], acc2);
            acc3 = fma2(p3, w2[4 * q + 3], acc3);
        }
        u64 s2 = add2(add2(acc0, acc1), add2(acc2, acc3));
        s2 = add2(s2, pk2(pv0, pv1));
        float s0, s1;
        upk2(s0, s1, s2);

        // i:[0,64) f:[64,128) g:[128,192) o:[192,256)  (warp-uniform branch)
        float v0, v1;
        if (g < 128 || g >= 192) { v0 = sigm_f(s0); v1 = sigm_f(s1); }
        else                     { v0 = tanh_f(s0); v1 = tanh_f(s1); }
        gate2_s[g] = make_float2(v0, v1);
        __syncthreads();

        if (g < 64) {
            float2 iv = gate2_s[g];
            float2 fv = gate2_s[64 + g];
            float2 gv = gate2_s[128 + g];
            float2 ov = gate2_s[192 + g];
            u64 ig = mul2(pk2(iv.x, iv.y), pk2(gv.x, gv.y));
            c2 = fma2(pk2(fv.x, fv.y), c2, ig);
            float c0, c1;
            upk2(c0, c1, c2);
            float h0 = ov.x * tanh_f(c0);
            float h1 = ov.y * tanh_f(c1);
            h2_s[g] = make_float2(h0, h1);
            if (MODE < 2) {
                hout[((size_t)batch0 * Tlen + t) * Hdim + g] = h0;
                hout[((size_t)batch1 * Tlen + t) * Hdim + g] = h1;
            }
        }
        __syncthreads();

        if (MODE == 2 && g < 32) {       // warp 0: FC head for both batches
            float2 ha = h2_s[g];
            float2 hb = h2_s[g + 32];
            float sx = ha.x * fwa + hb.x * fwb;
            float sy = ha.y * fwa + hb.y * fwb;
#pragma unroll
            for (int d = 16; d > 0; d >>= 1) {
                sx += __shfl_down_sync(0xffffffffu, sx, d);
                sy += __shfl_down_sync(0xffffffffu, sy, d);
            }
            if (g == 0) {
                out[(size_t)batch0 * Tlen + t] = sx + fcb;
                out[(size_t)batch1 * Tlen + t] = sy + fcb;
            }
        }
    }
}

extern "C" void kernel_launch(void* const* d_in, const int* in_sizes, int n_in,
                              void* d_out, int out_size)
{
    const float* x    = (const float*)d_in[0];
    const float* wih0 = (const float*)d_in[1];
    const float* whh0 = (const float*)d_in[2];
    const float* bih0 = (const float*)d_in[3];
    const float* bhh0 = (const float*)d_in[4];
    const float* wih1 = (const float*)d_in[5];
    const float* whh1 = (const float*)d_in[6];
    const float* bih1 = (const float*)d_in[7];
    const float* bhh1 = (const float*)d_in[8];
    const float* wih2 = (const float*)d_in[9];
    const float* whh2 = (const float*)d_in[10];
    const float* bih2 = (const float*)d_in[11];
    const float* bhh2 = (const float*)d_in[12];
    const float* fcw  = (const float*)d_in[13];
    const float* fcb  = (const float*)d_in[14];
    float* out = (float*)d_out;

    cudaFuncSetAttribute(gemm_mma_kernel,
                         cudaFuncAttributeMaxDynamicSharedMemorySize, GSM_TOTAL);

    const int gblocks = Mrows / 64;     // 8192

    // Layer 0
    gemm_mma_kernel<<<gblocks, 256, GSM_TOTAL>>>(x, 0, wih0, bih0, bhh0, Idim);
    lstm_rec_kernel<0><<<Bsz / 2, 256>>>(whh0, nullptr, nullptr, nullptr);
    // Layer 1
    gemm_mma_kernel<<<gblocks, 256, GSM_TOTAL>>>(nullptr, 1, wih1, bih1, bhh1, Hdim);
    lstm_rec_kernel<1><<<Bsz / 2, 256>>>(whh1, nullptr, nullptr, nullptr);
    // Layer 2 + fused FC head
    gemm_mma_kernel<<<gblocks, 256, GSM_TOTAL>>>(nullptr, 2, wih2, bih2, bhh2, Hdim);
    lstm_rec_kernel<2><<<Bsz / 2, 256>>>(whh2, fcw, fcb, out);
}

// round 15
// speedup vs baseline: 1.1822x; 1.1822x over previous
#include <cuda_runtime.h>
#include <cuda_bf16.h>
#include <cstdint>

#define Bsz  256
#define Tlen 2048
#define Idim 128
#define Hdim 64
#define Gdim 256                       // 4*H
#define Mrows (Bsz * Tlen)             // 524288

// Scratch (static device arrays: allocation-free per harness rules)
__device__ float g_pre[(size_t)Mrows * Gdim];   // 512 MiB: pre-activations
__device__ float g_h0 [(size_t)Mrows * Hdim];   // 128 MiB: layer output ping
__device__ float g_h1 [(size_t)Mrows * Hdim];   // 128 MiB: layer output pong

__device__ __forceinline__ float sigm_f(float x) {
    return 1.0f / (1.0f + __expf(-x));
}
__device__ __forceinline__ float tanh_f(float x) {
    return 2.0f / (1.0f + __expf(-2.0f * x)) - 1.0f;
}

// ---------------------------------------------------------------------------
// packed f32x2 helpers (base-profile sm_100+ PTX, plain sm_103 target OK)
// ---------------------------------------------------------------------------
typedef unsigned long long u64;

__device__ __forceinline__ void upk2(float& x, float& y, u64 v) {
    asm("mov.b64 {%0, %1}, %2;" : "=f"(x), "=f"(y) : "l"(v));
}
__device__ __forceinline__ u64 fma2(u64 a, u64 b, u64 c) {
    u64 d;
    asm("fma.rn.f32x2 %0, %1, %2, %3;" : "=l"(d) : "l"(a), "l"(b), "l"(c));
    return d;
}
__device__ __forceinline__ u64 add2(u64 a, u64 b) {
    u64 d;
    asm("add.rn.f32x2 %0, %1, %2;" : "=l"(d) : "l"(a), "l"(b));
    return d;
}
__device__ __forceinline__ void lds_v2(u64& a, u64& b, uint32_t addr) {
    asm volatile("ld.shared.v2.u64 {%0, %1}, [%2];"
                 : "=l"(a), "=l"(b) : "r"(addr));
}

// ---------------------------------------------------------------------------
// mma.sync helpers (baseline PTX — works on plain sm_103 target)
// ---------------------------------------------------------------------------
__device__ __forceinline__ void ldsm_x4(uint32_t* r, uint32_t addr) {
    asm volatile("ldmatrix.sync.aligned.m8n8.x4.shared.b16 {%0,%1,%2,%3}, [%4];"
                 : "=r"(r[0]), "=r"(r[1]), "=r"(r[2]), "=r"(r[3]) : "r"(addr));
}
__device__ __forceinline__ void mma16816(float* d, const uint32_t* a, const uint32_t* b) {
    asm volatile(
        "mma.sync.aligned.m16n8k16.row.col.f32.bf16.bf16.f32 "
        "{%0,%1,%2,%3}, {%4,%5,%6,%7}, {%8,%9}, {%0,%1,%2,%3};"
        : "+f"(d[0]), "+f"(d[1]), "+f"(d[2]), "+f"(d[3])
        : "r"(a[0]), "r"(a[1]), "r"(a[2]), "r"(a[3]), "r"(b[0]), "r"(b[1]));
}

// ===========================================================================
// GEMM: g_pre[m, n] = sum_k A[m,k]*W[n,k] + bih[n] + bhh[n]
// Block tile M=64 x N=256 (full N), K-chunks of 32, split-bf16 3-term.
// (unchanged — measured ~0.9 ms total for 3 layers)
// ===========================================================================
#define SMA_HI 0
#define SMA_LO 5120
#define SMW_HI 10240
#define SMW_LO 30720
#define GSM_TOTAL 51200

__global__ __launch_bounds__(256, 2) void gemm_mma_kernel(
    const float* __restrict__ Aext, int sel,
    const float* __restrict__ W,
    const float* __restrict__ bih, const float* __restrict__ bhh,
    int K)
{
    extern __shared__ char smem[];
    const uint32_t sbase = (uint32_t)__cvta_generic_to_shared(smem);

    const float* A = (sel == 0) ? Aext : ((sel == 1) ? g_h0 : g_h1);

    const int t   = threadIdx.x;
    const int wid = t >> 5;
    const int lid = t & 31;
    const int wm  = wid >> 2;          // 0..1 : warp row   (32 M each)
    const int wn  = wid & 3;           // 0..3 : warp col   (64 N each)
    const size_t m0 = (size_t)blockIdx.x * 64;

    float acc[2][8][4];
#pragma unroll
    for (int i = 0; i < 2; i++)
#pragma unroll
        for (int j = 0; j < 8; j++)
#pragma unroll
            for (int v = 0; v < 4; v++) acc[i][j][v] = 0.0f;

    // per-lane ldmatrix address components (stride 40 bf16 = 80B per row)
    const int rowA = wm * 32 + (lid & 7) + ((lid >> 3) & 1) * 8;
    const int colA = (lid >> 4) * 8;
    const int rowB = wn * 64 + (lid >> 4) * 8 + (lid & 7);
    const int colB = ((lid >> 3) & 1) * 8;

    const int nchunks = K >> 5;
    for (int c = 0; c < nchunks; c++) {
        const int k0 = c << 5;

        // ---- load + split-convert A tile (64 x 32): 512 float4, 2/thread ----
#pragma unroll
        for (int i = 0; i < 2; i++) {
            int f   = t + i * 256;
            int row = f >> 3;
            int c4  = (f & 7) << 2;
            float4 v = *(const float4*)&A[(m0 + row) * K + k0 + c4];
            __nv_bfloat162 h0 = __floats2bfloat162_rn(v.x, v.y);
            __nv_bfloat162 h1 = __floats2bfloat162_rn(v.z, v.w);
            __nv_bfloat162 l0 = __floats2bfloat162_rn(v.x - __bfloat162float(h0.x),
                                                      v.y - __bfloat162float(h0.y));
            __nv_bfloat162 l1 = __floats2bfloat162_rn(v.z - __bfloat162float(h1.x),
                                                      v.w - __bfloat162float(h1.y));
            uint32_t off = (uint32_t)(row * 40 + c4) * 2;
            *(uint2*)(smem + SMA_HI + off) =
                make_uint2(*(uint32_t*)&h0, *(uint32_t*)&h1);
            *(uint2*)(smem + SMA_LO + off) =
                make_uint2(*(uint32_t*)&l0, *(uint32_t*)&l1);
        }
        // ---- load + split-convert W tile (256 x 32): 2048 float4, 8/thread ----
#pragma unroll
        for (int i = 0; i < 8; i++) {
            int f   = t + i * 256;
            int row = f >> 3;
            int c4  = (f & 7) << 2;
            float4 v = *(const float4*)&W[(size_t)row * K + k0 + c4];
            __nv_bfloat162 h0 = __floats2bfloat162_rn(v.x, v.y);
            __nv_bfloat162 h1 = __floats2bfloat162_rn(v.z, v.w);
            __nv_bfloat162 l0 = __floats2bfloat162_rn(v.x - __bfloat162float(h0.x),
                                                      v.y - __bfloat162float(h0.y));
            __nv_bfloat162 l1 = __floats2bfloat162_rn(v.z - __bfloat162float(h1.x),
                                                      v.w - __bfloat162float(h1.y));
            uint32_t off = (uint32_t)(row * 40 + c4) * 2;
            *(uint2*)(smem + SMW_HI + off) =
                make_uint2(*(uint32_t*)&h0, *(uint32_t*)&h1);
            *(uint2*)(smem + SMW_LO + off) =
                make_uint2(*(uint32_t*)&l0, *(uint32_t*)&l1);
        }
        __syncthreads();

        // ---- mma over the 32-deep chunk (2 k16 steps, 3 precision terms) ----
#pragma unroll
        for (int kt = 0; kt < 2; kt++) {
            uint32_t afh[2][4], afl[2][4];
#pragma unroll
            for (int mt = 0; mt < 2; mt++) {
                uint32_t ao = (uint32_t)((rowA + mt * 16) * 40 + colA + kt * 16) * 2;
                ldsm_x4(afh[mt], sbase + SMA_HI + ao);
                ldsm_x4(afl[mt], sbase + SMA_LO + ao);
            }
#pragma unroll
            for (int nt2 = 0; nt2 < 4; nt2++) {
                uint32_t bo = (uint32_t)((rowB + nt2 * 16) * 40 + colB + kt * 16) * 2;
                uint32_t bfh[4], bfl[4];
                ldsm_x4(bfh, sbase + SMW_HI + bo);
                ldsm_x4(bfl, sbase + SMW_LO + bo);
#pragma unroll
                for (int mt = 0; mt < 2; mt++)
#pragma unroll
                    for (int half = 0; half < 2; half++) {
                        int nt = nt2 * 2 + half;
                        mma16816(acc[mt][nt], afh[mt], &bfh[half * 2]);  // hi*hi
                        mma16816(acc[mt][nt], afh[mt], &bfl[half * 2]);  // hi*lo
                        mma16816(acc[mt][nt], afl[mt], &bfh[half * 2]);  // lo*hi
                    }
            }
        }
        __syncthreads();
    }

    // ---- epilogue: d[row, n] + bias ----
    const int g  = lid >> 2;
    const int tg = lid & 3;
#pragma unroll
    for (int nt = 0; nt < 8; nt++) {
        int n = wn * 64 + nt * 8 + tg * 2;
        float b0 = bih[n]     + bhh[n];
        float b1 = bih[n + 1] + bhh[n + 1];
        size_t row0 = m0 + wm * 32 + g;
#pragma unroll
        for (int mt = 0; mt < 2; mt++) {
            size_t r0 = row0 + mt * 16;
            float2 o0 = make_float2(acc[mt][nt][0] + b0, acc[mt][nt][1] + b1);
            float2 o1 = make_float2(acc[mt][nt][2] + b0, acc[mt][nt][3] + b1);
            *(float2*)&g_pre[r0 * Gdim + n]       = o0;
            *(float2*)&g_pre[(r0 + 8) * Gdim + n] = o1;
        }
    }
}

// ===========================================================================
// Recurrent layer: round-9 structure (512 threads, two independent
// 256-thread groups, one batch each -> 16 warps/SM) with the dot product
// packed along the HIDDEN axis: w2[k] = (w[2k], w[2k+1]) is just the weight
// row reinterpreted as u64 (32 b64 regs = 64 regs, same pressure as round 9),
// h read as packed u64 pairs. 32 FFMA2 replaces 64 FFMA.
// MODE 0 -> g_h0; MODE 1 -> g_h1; MODE 2 -> fused FC head into out.
// ===========================================================================
template <int MODE>
__global__ __launch_bounds__(512) void lstm_rec_kernel(
    const float* __restrict__ w_hh,
    const float* __restrict__ fc_w, const float* __restrict__ fc_b,
    float* __restrict__ out)
{
    __shared__ __align__(16) float h_s[2][64];
    __shared__ float gate_s[2][256];

    const int tid = threadIdx.x;
    const int bb  = tid >> 8;            // batch group 0/1
    const int gg  = tid & 255;           // gate index within group
    const int b2  = blockIdx.x;          // handles batches 2*b2, 2*b2+1
    const int batch = 2 * b2 + bb;

    // packed weights: row of 64 fp32 reinterpreted as 32 u64 (lo=w[2k], hi=w[2k+1])
    u64 w2[32];
    {
        const u64* wrow = (const u64*)(w_hh + (size_t)gg * 64);
#pragma unroll
        for (int k = 0; k < 32; k++) w2[k] = wrow[k];
    }

    float c = 0.0f;                      // cell state (threads gg<64 use it)
    if (gg < 64) h_s[bb][gg] = 0.0f;

    float fwa = 0.0f, fwb = 0.0f, fcb = 0.0f;
    if (MODE == 2 && gg < 32) {
        fwa = fc_w[gg];
        fwb = fc_w[gg + 32];
        fcb = fc_b[0];
    }
    __syncthreads();

    const float* pre = g_pre + ((size_t)batch * Tlen) * Gdim + gg;
    float* hout = (MODE == 0) ? g_h0 : g_h1;

    const uint32_t haddr = (uint32_t)__cvta_generic_to_shared(h_s[bb]);

    float pn = pre[0];

    for (int t = 0; t < Tlen; t++) {
        float pv = pn;
        if (t + 1 < Tlen) pn = pre[(size_t)(t + 1) * Gdim];   // prefetch

        // packed dot product: 32 FFMA2, 16 x 16B LDS (broadcast), 4 acc chains
        u64 acc0 = 0, acc1 = 0, acc2 = 0, acc3 = 0;
#pragma unroll
        for (int q = 0; q < 8; q++) {
            u64 p0, p1, p2, p3;
            lds_v2(p0, p1, haddr + q * 32);
            lds_v2(p2, p3, haddr + q * 32 + 16);
            acc0 = fma2(p0, w2[4 * q + 0], acc0);
            acc1 = fma2(p1, w2[4 * q + 1], acc1);
            acc2 = fma2(p2, w2[4 * q + 2], acc2);
            acc3 = fma2(p3, w2[4 * q + 3], acc3);
        }
        u64 s2 = add2(add2(acc0, acc1), add2(acc2, acc3));
        float sa, sb;
        upk2(sa, sb, s2);
        float s = pv + (sa + sb);

        // i:[0,64) f:[64,128) g:[128,192) o:[192,256)  (warp-uniform branch)
        float v = (gg < 128 || gg >= 192) ? sigm_f(s) : tanh_f(s);
        gate_s[bb][gg] = v;
        __syncthreads();

        if (gg < 64) {
            float iv = gate_s[bb][gg];
            float fv = gate_s[bb][64 + gg];
            float gv = gate_s[bb][128 + gg];
            float ov = gate_s[bb][192 + gg];
            c = fv * c + iv * gv;
            float h = ov * tanh_f(c);
            h_s[bb][gg] = h;
            if (MODE < 2)
                hout[((size_t)batch * Tlen + t) * Hdim + gg] = h;
        }
        __syncthreads();

        if (MODE == 2 && gg < 32) {      // warp 0 of each group -> FC head
            float sfc = h_s[bb][gg] * fwa + h_s[bb][gg + 32] * fwb;
            sfc += __shfl_down_sync(0xffffffffu, sfc, 16);
            sfc += __shfl_down_sync(0xffffffffu, sfc, 8);
            sfc += __shfl_down_sync(0xffffffffu, sfc, 4);
            sfc += __shfl_down_sync(0xffffffffu, sfc, 2);
            sfc += __shfl_down_sync(0xffffffffu, sfc, 1);
            if (gg == 0) out[(size_t)batch * Tlen + t] = sfc + fcb;
        }
    }
}

extern "C" void kernel_launch(void* const* d_in, const int* in_sizes, int n_in,
                              void* d_out, int out_size)
{
    const float* x    = (const float*)d_in[0];
    const float* wih0 = (const float*)d_in[1];
    const float* whh0 = (const float*)d_in[2];
    const float* bih0 = (const float*)d_in[3];
    const float* bhh0 = (const float*)d_in[4];
    const float* wih1 = (const float*)d_in[5];
    const float* whh1 = (const float*)d_in[6];
    const float* bih1 = (const float*)d_in[7];
    const float* bhh1 = (const float*)d_in[8];
    const float* wih2 = (const float*)d_in[9];
    const float* whh2 = (const float*)d_in[10];
    const float* bih2 = (const float*)d_in[11];
    const float* bhh2 = (const float*)d_in[12];
    const float* fcw  = (const float*)d_in[13];
    const float* fcb  = (const float*)d_in[14];
    float* out = (float*)d_out;

    cudaFuncSetAttribute(gemm_mma_kernel,
                         cudaFuncAttributeMaxDynamicSharedMemorySize, GSM_TOTAL);

    const int gblocks = Mrows / 64;     // 8192

    // Layer 0
    gemm_mma_kernel<<<gblocks, 256, GSM_TOTAL>>>(x, 0, wih0, bih0, bhh0, Idim);
    lstm_rec_kernel<0><<<Bsz / 2, 512>>>(whh0, nullptr, nullptr, nullptr);
    // Layer 1
    gemm_mma_kernel<<<gblocks, 256, GSM_TOTAL>>>(nullptr, 1, wih1, bih1, bhh1, Hdim);
    lstm_rec_kernel<1><<<Bsz / 2, 512>>>(whh1, nullptr, nullptr, nullptr);
    // Layer 2 + fused FC head
    gemm_mma_kernel<<<gblocks, 256, GSM_TOTAL>>>(nullptr, 2, wih2, bih2, bhh2, Hdim);
    lstm_rec_kernel<2><<<Bsz / 2, 512>>>(whh2, fcw, fcb, out);
}